// round 2
// baseline (speedup 1.0000x reference)
#include <cuda_runtime.h>

// Problem constants
#define B_ 2
#define P_ 2048
#define M_ 1024
#define H_ 16
#define D_ 64
#define ROWS_ (B_*P_)          // 4096
#define N3M_ (3*M_)            // 3072

// Scratch (allocation-free rule: __device__ globals)
__device__ float g_qkv[(size_t)ROWS_ * N3M_];   // [4096][3072]
__device__ float g_z[(size_t)ROWS_ * M_];       // [4096][1024]

// ---------------------------------------------------------------------------
// SGEMM with bias: C[Mr,Nc] = A[Mr,Kd] @ B[Kd,Nc] + bias[Nc]
// BM=BN=128, BK=16, 256 threads, 8x8 per-thread tile. All dims divide evenly.
// ---------------------------------------------------------------------------
__global__ __launch_bounds__(256) void sgemm_bias_kernel(
    const float* __restrict__ A, const float* __restrict__ Bm,
    const float* __restrict__ bias, float* __restrict__ C,
    int Mr, int Nc, int Kd)
{
    __shared__ float As[16][128];   // A^T in smem
    __shared__ float Bs[16][128];

    const int tid = threadIdx.x;
    const int bm = blockIdx.y * 128;
    const int bn = blockIdx.x * 128;
    const int tx = tid & 15;       // 16 col-groups
    const int ty = tid >> 4;       // 16 row-groups

    float acc[8][8];
#pragma unroll
    for (int i = 0; i < 8; i++)
#pragma unroll
        for (int j = 0; j < 8; j++) acc[i][j] = 0.f;

    for (int k0 = 0; k0 < Kd; k0 += 16) {
        // A tile: 128 rows x 16 k = 512 float4 (4 per row)
#pragma unroll
        for (int l = 0; l < 2; ++l) {
            int fi = tid + l * 256;
            int row = fi >> 2;
            int k4 = fi & 3;
            float4 v = *reinterpret_cast<const float4*>(
                A + (size_t)(bm + row) * Kd + k0 + k4 * 4);
            As[k4 * 4 + 0][row] = v.x;
            As[k4 * 4 + 1][row] = v.y;
            As[k4 * 4 + 2][row] = v.z;
            As[k4 * 4 + 3][row] = v.w;
        }
        // B tile: 16 rows x 128 cols = 512 float4 (32 per row)
#pragma unroll
        for (int l = 0; l < 2; ++l) {
            int fi = tid + l * 256;
            int row = fi >> 5;
            int c4 = fi & 31;
            *reinterpret_cast<float4*>(&Bs[row][c4 * 4]) =
                *reinterpret_cast<const float4*>(
                    Bm + (size_t)(k0 + row) * Nc + bn + c4 * 4);
        }
        __syncthreads();

#pragma unroll
        for (int kk = 0; kk < 16; kk++) {
            float4 a0 = *reinterpret_cast<const float4*>(&As[kk][ty * 8]);
            float4 a1 = *reinterpret_cast<const float4*>(&As[kk][ty * 8 + 4]);
            float4 b0 = *reinterpret_cast<const float4*>(&Bs[kk][tx * 8]);
            float4 b1 = *reinterpret_cast<const float4*>(&Bs[kk][tx * 8 + 4]);
            float ra[8] = {a0.x, a0.y, a0.z, a0.w, a1.x, a1.y, a1.z, a1.w};
            float rb[8] = {b0.x, b0.y, b0.z, b0.w, b1.x, b1.y, b1.z, b1.w};
#pragma unroll
            for (int i = 0; i < 8; i++)
#pragma unroll
                for (int j = 0; j < 8; j++)
                    acc[i][j] += ra[i] * rb[j];
        }
        __syncthreads();
    }

#pragma unroll
    for (int i = 0; i < 8; i++) {
        int r = bm + ty * 8 + i;
#pragma unroll
        for (int j4 = 0; j4 < 2; j4++) {
            int c = bn + tx * 8 + j4 * 4;
            float4 v;
            v.x = acc[i][j4 * 4 + 0] + bias[c + 0];
            v.y = acc[i][j4 * 4 + 1] + bias[c + 1];
            v.z = acc[i][j4 * 4 + 2] + bias[c + 2];
            v.w = acc[i][j4 * 4 + 3] + bias[c + 3];
            *reinterpret_cast<float4*>(C + (size_t)r * Nc + c) = v;
        }
    }
}

// ---------------------------------------------------------------------------
// Flash-style causal attention. One block = (b, h, 64-row q-tile).
// k-tiles of 32. Online softmax. Reads g_qkv, writes g_z.
// ---------------------------------------------------------------------------
__global__ __launch_bounds__(256) void attn_kernel()
{
    __shared__ float Qs[64][65];   // padded: conflict-free row reads
    __shared__ float KT[64][36];   // K transposed [d][c], padded, float4-alignable
    __shared__ float Ss[64][33];   // scores / probabilities
    __shared__ float Vs[32][64];

    const int tid = threadIdx.x;
    const int bh = blockIdx.y;          // b*H + h
    const int b = bh >> 4;
    const int h = bh & 15;
    const int q0 = blockIdx.x * 64;

    // ---- load Q tile (pre-scaled by 1/sqrt(D)=0.125) ----
#pragma unroll
    for (int l = 0; l < 4; l++) {
        int fi = tid + l * 256;
        int row = fi >> 4;
        int d4 = fi & 15;
        float4 v = *reinterpret_cast<const float4*>(
            g_qkv + (size_t)(b * P_ + q0 + row) * N3M_ + h * 64 + d4 * 4);
        Qs[row][d4 * 4 + 0] = v.x * 0.125f;
        Qs[row][d4 * 4 + 1] = v.y * 0.125f;
        Qs[row][d4 * 4 + 2] = v.z * 0.125f;
        Qs[row][d4 * 4 + 3] = v.w * 0.125f;
    }

    // PV / softmax mapping: 4 threads per row
    const int rp = tid >> 2;
    const int quad = tid & 3;
    float4 o4[4];
#pragma unroll
    for (int i = 0; i < 4; i++) o4[i] = make_float4(0.f, 0.f, 0.f, 0.f);
    float m = -1e30f, lsum = 0.f;

    // S-compute mapping: 2 rows x 4 cols per thread
    const int g = tid >> 3;
    const int r0 = g * 2, r1 = g * 2 + 1;
    const int cq = (tid & 7) * 4;

    const int nkt = q0 / 32 + 2;    // causal tile count
    __syncthreads();

    for (int kt = 0; kt < nkt; ++kt) {
        const int k0 = kt * 32;

        // ---- load K tile transposed ----
#pragma unroll
        for (int l = 0; l < 2; l++) {
            int fi = tid + l * 256;
            int krow = fi >> 4;
            int d4 = fi & 15;
            float4 v = *reinterpret_cast<const float4*>(
                g_qkv + (size_t)(b * P_ + k0 + krow) * N3M_ + M_ + h * 64 + d4 * 4);
            KT[d4 * 4 + 0][krow] = v.x;
            KT[d4 * 4 + 1][krow] = v.y;
            KT[d4 * 4 + 2][krow] = v.z;
            KT[d4 * 4 + 3][krow] = v.w;
        }
        __syncthreads();

        // ---- S = Q K^T (2 rows x 4 cols per thread) ----
        float s0[4] = {0.f, 0.f, 0.f, 0.f};
        float s1[4] = {0.f, 0.f, 0.f, 0.f};
#pragma unroll 16
        for (int d = 0; d < 64; d++) {
            float qa = Qs[r0][d];
            float qb = Qs[r1][d];
            float4 kv = *reinterpret_cast<const float4*>(&KT[d][cq]);
            s0[0] += qa * kv.x; s0[1] += qa * kv.y;
            s0[2] += qa * kv.z; s0[3] += qa * kv.w;
            s1[0] += qb * kv.x; s1[1] += qb * kv.y;
            s1[2] += qb * kv.z; s1[3] += qb * kv.w;
        }
#pragma unroll
        for (int j = 0; j < 4; j++) {
            int c = cq + j;
            Ss[r0][c] = (k0 + c <= q0 + r0) ? s0[j] : -1e30f;
            Ss[r1][c] = (k0 + c <= q0 + r1) ? s1[j] : -1e30f;
        }
        __syncthreads();

        // ---- online softmax: read phase (4 threads/row, redundant) ----
        float rowm = -1e30f;
#pragma unroll
        for (int c = 0; c < 32; c++) rowm = fmaxf(rowm, Ss[rp][c]);
        float m_new = fmaxf(m, rowm);
        float corr = __expf(m - m_new);
        float psum = 0.f;
#pragma unroll
        for (int c = 0; c < 32; c++) psum += __expf(Ss[rp][c] - m_new);
        float p[8];
#pragma unroll
        for (int j = 0; j < 8; j++)
            p[j] = __expf(Ss[rp][quad * 8 + j] - m_new);
        lsum = lsum * corr + psum;
        m = m_new;
#pragma unroll
        for (int i = 0; i < 4; i++) {
            o4[i].x *= corr; o4[i].y *= corr;
            o4[i].z *= corr; o4[i].w *= corr;
        }
        __syncthreads();   // all reads of raw S done

        // ---- write P back + load V tile ----
#pragma unroll
        for (int j = 0; j < 8; j++) Ss[rp][quad * 8 + j] = p[j];
#pragma unroll
        for (int l = 0; l < 2; l++) {
            int fi = tid + l * 256;
            int krow = fi >> 4;
            int d4 = fi & 15;
            *reinterpret_cast<float4*>(&Vs[krow][d4 * 4]) =
                *reinterpret_cast<const float4*>(
                    g_qkv + (size_t)(b * P_ + k0 + krow) * N3M_ + 2 * M_ + h * 64 + d4 * 4);
        }
        __syncthreads();

        // ---- O += P @ V  (each thread: 1 row x 16 d-cols) ----
#pragma unroll 8
        for (int c = 0; c < 32; c++) {
            float pv = Ss[rp][c];
#pragma unroll
            for (int i = 0; i < 4; i++) {
                float4 v = *reinterpret_cast<const float4*>(
                    &Vs[c][quad * 16 + i * 4]);
                o4[i].x += pv * v.x; o4[i].y += pv * v.y;
                o4[i].z += pv * v.z; o4[i].w += pv * v.w;
            }
        }
        __syncthreads();   // before KT/Ss/Vs are overwritten
    }

    // ---- normalize and write z[b, q, h, d] ----
    float inv = 1.f / lsum;
#pragma unroll
    for (int i = 0; i < 4; i++) {
        float4 v = o4[i];
        v.x *= inv; v.y *= inv; v.z *= inv; v.w *= inv;
        *reinterpret_cast<float4*>(
            g_z + (size_t)(b * P_ + q0 + rp) * M_ + h * 64 + quad * 16 + i * 4) = v;
    }
}

// ---------------------------------------------------------------------------
extern "C" void kernel_launch(void* const* d_in, const int* in_sizes, int n_in,
                              void* d_out, int out_size)
{
    (void)in_sizes; (void)n_in; (void)out_size;
    const float* x      = (const float*)d_in[0];
    const float* W_attn = (const float*)d_in[1];
    const float* b_attn = (const float*)d_in[2];
    const float* W_proj = (const float*)d_in[3];
    const float* b_proj = (const float*)d_in[4];
    float* out = (float*)d_out;

    void* qkvp = nullptr;
    void* zp = nullptr;
    cudaGetSymbolAddress(&qkvp, g_qkv);
    cudaGetSymbolAddress(&zp, g_z);

    dim3 blk(256);
    // QKV projection: [4096,1024] @ [1024,3072] + b_attn
    sgemm_bias_kernel<<<dim3(N3M_ / 128, ROWS_ / 128), blk>>>(
        x, W_attn, b_attn, (float*)qkvp, ROWS_, N3M_, M_);
    // causal attention per (b,h,q-tile)
    attn_kernel<<<dim3(P_ / 64, B_ * H_), blk>>>();
    // output projection: [4096,1024] @ [1024,1024] + b_proj
    sgemm_bias_kernel<<<dim3(M_ / 128, ROWS_ / 128), blk>>>(
        (const float*)zp, W_proj, b_proj, out, ROWS_, M_, M_);
}

// round 3
// speedup vs baseline: 1.9152x; 1.9152x over previous
#include <cuda_runtime.h>

// Problem constants
#define B_ 2
#define P_ 2048
#define M_ 1024
#define H_ 16
#define D_ 64
#define ROWS_ (B_*P_)          // 4096
#define N3M_ (3*M_)            // 3072

// Scratch (allocation-free rule: __device__ globals)
__device__ float g_qkv[(size_t)ROWS_ * N3M_];   // [4096][3072]
__device__ float g_z[(size_t)ROWS_ * M_];       // [4096][1024]

// ---------------------------------------------------------------------------
// SGEMM with bias: C[Mr,Nc] = A[Mr,Kd] @ B[Kd,Nc] + bias[Nc]
// BM=BN=128, BK=16, 256 threads, 8x8 per-thread tile. All dims divide evenly.
// ---------------------------------------------------------------------------
__global__ __launch_bounds__(256) void sgemm_bias_kernel(
    const float* __restrict__ A, const float* __restrict__ Bm,
    const float* __restrict__ bias, float* __restrict__ C,
    int Mr, int Nc, int Kd)
{
    __shared__ float As[16][128];   // A^T in smem
    __shared__ float Bs[16][128];

    const int tid = threadIdx.x;
    const int bm = blockIdx.y * 128;
    const int bn = blockIdx.x * 128;
    const int tx = tid & 15;
    const int ty = tid >> 4;

    float acc[8][8];
#pragma unroll
    for (int i = 0; i < 8; i++)
#pragma unroll
        for (int j = 0; j < 8; j++) acc[i][j] = 0.f;

    for (int k0 = 0; k0 < Kd; k0 += 16) {
#pragma unroll
        for (int l = 0; l < 2; ++l) {
            int fi = tid + l * 256;
            int row = fi >> 2;
            int k4 = fi & 3;
            float4 v = *reinterpret_cast<const float4*>(
                A + (size_t)(bm + row) * Kd + k0 + k4 * 4);
            As[k4 * 4 + 0][row] = v.x;
            As[k4 * 4 + 1][row] = v.y;
            As[k4 * 4 + 2][row] = v.z;
            As[k4 * 4 + 3][row] = v.w;
        }
#pragma unroll
        for (int l = 0; l < 2; ++l) {
            int fi = tid + l * 256;
            int row = fi >> 5;
            int c4 = fi & 31;
            *reinterpret_cast<float4*>(&Bs[row][c4 * 4]) =
                *reinterpret_cast<const float4*>(
                    Bm + (size_t)(k0 + row) * Nc + bn + c4 * 4);
        }
        __syncthreads();

#pragma unroll
        for (int kk = 0; kk < 16; kk++) {
            float4 a0 = *reinterpret_cast<const float4*>(&As[kk][ty * 8]);
            float4 a1 = *reinterpret_cast<const float4*>(&As[kk][ty * 8 + 4]);
            float4 b0 = *reinterpret_cast<const float4*>(&Bs[kk][tx * 8]);
            float4 b1 = *reinterpret_cast<const float4*>(&Bs[kk][tx * 8 + 4]);
            float ra[8] = {a0.x, a0.y, a0.z, a0.w, a1.x, a1.y, a1.z, a1.w};
            float rb[8] = {b0.x, b0.y, b0.z, b0.w, b1.x, b1.y, b1.z, b1.w};
#pragma unroll
            for (int i = 0; i < 8; i++)
#pragma unroll
                for (int j = 0; j < 8; j++)
                    acc[i][j] += ra[i] * rb[j];
        }
        __syncthreads();
    }

#pragma unroll
    for (int i = 0; i < 8; i++) {
        int r = bm + ty * 8 + i;
#pragma unroll
        for (int j4 = 0; j4 < 2; j4++) {
            int c = bn + tx * 8 + j4 * 4;
            float4 v;
            v.x = acc[i][j4 * 4 + 0] + bias[c + 0];
            v.y = acc[i][j4 * 4 + 1] + bias[c + 1];
            v.z = acc[i][j4 * 4 + 2] + bias[c + 2];
            v.w = acc[i][j4 * 4 + 3] + bias[c + 3];
            *reinterpret_cast<float4*>(C + (size_t)r * Nc + c) = v;
        }
    }
}

// ---------------------------------------------------------------------------
// Flash-style causal attention v2. One block = (b, h, 128-row q-tile).
// k-tiles of 128. 256 threads, 8x8 register tile for S, 8x4 for O.
// Softmax entirely in registers via shfl across 16-thread row groups.
// Dynamic smem: Qt[64][132] + Kt[64][132] + Ps[128][132] + Vs[128][68].
// ---------------------------------------------------------------------------
#define AT_SMEM_FLOATS (64*132 + 64*132 + 128*132 + 128*68)
#define AT_SMEM_BYTES  (AT_SMEM_FLOATS * 4)

__global__ __launch_bounds__(256) void attn2_kernel(
    const float* __restrict__ qkv, float* __restrict__ z)
{
    extern __shared__ float sm[];
    float* Qt = sm;                       // [64][132]  (d-major, transposed)
    float* Kt = Qt + 64 * 132;            // [64][132]
    float* Ps = Kt + 64 * 132;            // [128][132]
    float* Vs = Ps + 128 * 132;           // [128][68]

    const int tid = threadIdx.x;
    const int bh = blockIdx.y;            // b*H + h
    const int b = bh >> 4;
    const int h = bh & 15;
    const int qt = (int)gridDim.x - 1 - (int)blockIdx.x;  // heavy tiles first
    const int q0 = qt * 128;

    const int ty = tid >> 4;              // 0..15: 8 q-rows each
    const int tx = tid & 15;              // 0..15: 8 k-cols (S) / 4 d-cols (O)

    // ---- load Q tile transposed, pre-scaled by 1/sqrt(D)=0.125 ----
    const float* qbase = qkv + (size_t)(b * P_ + q0) * N3M_ + h * 64;
#pragma unroll
    for (int l2 = 0; l2 < 8; l2++) {
        int fi = tid + l2 * 256;
        int row = fi >> 4;
        int d4 = fi & 15;
        float4 v = *reinterpret_cast<const float4*>(qbase + (size_t)row * N3M_ + d4 * 4);
        Qt[(d4 * 4 + 0) * 132 + row] = v.x * 0.125f;
        Qt[(d4 * 4 + 1) * 132 + row] = v.y * 0.125f;
        Qt[(d4 * 4 + 2) * 132 + row] = v.z * 0.125f;
        Qt[(d4 * 4 + 3) * 132 + row] = v.w * 0.125f;
    }

    float4 O4[8];
#pragma unroll
    for (int i = 0; i < 8; i++) O4[i] = make_float4(0.f, 0.f, 0.f, 0.f);
    float mrow[8], lrow[8];
#pragma unroll
    for (int i = 0; i < 8; i++) { mrow[i] = -1e30f; lrow[i] = 0.f; }

    for (int kt = 0; kt <= qt; ++kt) {
        const int k0 = kt * 128;
        const float* kbase = qkv + (size_t)(b * P_ + k0) * N3M_ + M_ + h * 64;
        const float* vbase = qkv + (size_t)(b * P_ + k0) * N3M_ + 2 * M_ + h * 64;

        // ---- load K (transposed) and V tiles ----
#pragma unroll
        for (int l2 = 0; l2 < 8; l2++) {
            int fi = tid + l2 * 256;
            int row = fi >> 4;
            int d4 = fi & 15;
            float4 kv = *reinterpret_cast<const float4*>(kbase + (size_t)row * N3M_ + d4 * 4);
            Kt[(d4 * 4 + 0) * 132 + row] = kv.x;
            Kt[(d4 * 4 + 1) * 132 + row] = kv.y;
            Kt[(d4 * 4 + 2) * 132 + row] = kv.z;
            Kt[(d4 * 4 + 3) * 132 + row] = kv.w;
            float4 vv = *reinterpret_cast<const float4*>(vbase + (size_t)row * N3M_ + d4 * 4);
            *reinterpret_cast<float4*>(Vs + row * 68 + d4 * 4) = vv;
        }
        __syncthreads();

        // ---- S = Q K^T: 8x8 register tile per thread ----
        float s[8][8];
#pragma unroll
        for (int i = 0; i < 8; i++)
#pragma unroll
            for (int j = 0; j < 8; j++) s[i][j] = 0.f;

#pragma unroll 4
        for (int d = 0; d < 64; d++) {
            float4 a0 = *reinterpret_cast<const float4*>(Qt + d * 132 + ty * 8);
            float4 a1 = *reinterpret_cast<const float4*>(Qt + d * 132 + ty * 8 + 4);
            float4 b0 = *reinterpret_cast<const float4*>(Kt + d * 132 + tx * 8);
            float4 b1 = *reinterpret_cast<const float4*>(Kt + d * 132 + tx * 8 + 4);
            float ra[8] = {a0.x, a0.y, a0.z, a0.w, a1.x, a1.y, a1.z, a1.w};
            float rb[8] = {b0.x, b0.y, b0.z, b0.w, b1.x, b1.y, b1.z, b1.w};
#pragma unroll
            for (int i = 0; i < 8; i++)
#pragma unroll
                for (int j = 0; j < 8; j++)
                    s[i][j] += ra[i] * rb[j];
        }

        // ---- causal mask (only on the diagonal tile, k0 == q0) ----
        if (kt == qt) {
#pragma unroll
            for (int i = 0; i < 8; i++)
#pragma unroll
                for (int j = 0; j < 8; j++)
                    if (tx * 8 + j > ty * 8 + i) s[i][j] = -1e30f;
        }

        // ---- online softmax in registers (16-thread row groups) ----
#pragma unroll
        for (int i = 0; i < 8; i++) {
            float mx = s[i][0];
#pragma unroll
            for (int j = 1; j < 8; j++) mx = fmaxf(mx, s[i][j]);
            mx = fmaxf(mx, __shfl_xor_sync(0xffffffffu, mx, 1));
            mx = fmaxf(mx, __shfl_xor_sync(0xffffffffu, mx, 2));
            mx = fmaxf(mx, __shfl_xor_sync(0xffffffffu, mx, 4));
            mx = fmaxf(mx, __shfl_xor_sync(0xffffffffu, mx, 8));
            float mnew = fmaxf(mrow[i], mx);
            float corr = __expf(mrow[i] - mnew);
            mrow[i] = mnew;
            float sum = 0.f;
#pragma unroll
            for (int j = 0; j < 8; j++) {
                s[i][j] = __expf(s[i][j] - mnew);
                sum += s[i][j];
            }
            sum += __shfl_xor_sync(0xffffffffu, sum, 1);
            sum += __shfl_xor_sync(0xffffffffu, sum, 2);
            sum += __shfl_xor_sync(0xffffffffu, sum, 4);
            sum += __shfl_xor_sync(0xffffffffu, sum, 8);
            lrow[i] = lrow[i] * corr + sum;
            O4[i].x *= corr; O4[i].y *= corr;
            O4[i].z *= corr; O4[i].w *= corr;
        }

        // ---- stage P into smem ----
#pragma unroll
        for (int i = 0; i < 8; i++) {
            *reinterpret_cast<float4*>(Ps + (ty * 8 + i) * 132 + tx * 8) =
                make_float4(s[i][0], s[i][1], s[i][2], s[i][3]);
            *reinterpret_cast<float4*>(Ps + (ty * 8 + i) * 132 + tx * 8 + 4) =
                make_float4(s[i][4], s[i][5], s[i][6], s[i][7]);
        }
        __syncthreads();

        // ---- O += P @ V  (8 rows x 4 d-cols per thread, k-blocked by 4) ----
#pragma unroll 2
        for (int k = 0; k < 128; k += 4) {
            float4 vv0 = *reinterpret_cast<const float4*>(Vs + (k + 0) * 68 + tx * 4);
            float4 vv1 = *reinterpret_cast<const float4*>(Vs + (k + 1) * 68 + tx * 4);
            float4 vv2 = *reinterpret_cast<const float4*>(Vs + (k + 2) * 68 + tx * 4);
            float4 vv3 = *reinterpret_cast<const float4*>(Vs + (k + 3) * 68 + tx * 4);
#pragma unroll
            for (int i = 0; i < 8; i++) {
                float4 pp = *reinterpret_cast<const float4*>(Ps + (ty * 8 + i) * 132 + k);
                O4[i].x += pp.x * vv0.x + pp.y * vv1.x + pp.z * vv2.x + pp.w * vv3.x;
                O4[i].y += pp.x * vv0.y + pp.y * vv1.y + pp.z * vv2.y + pp.w * vv3.y;
                O4[i].z += pp.x * vv0.z + pp.y * vv1.z + pp.z * vv2.z + pp.w * vv3.z;
                O4[i].w += pp.x * vv0.w + pp.y * vv1.w + pp.z * vv2.w + pp.w * vv3.w;
            }
        }
        __syncthreads();
    }

    // ---- normalize and write z[b, q, h, d] ----
#pragma unroll
    for (int i = 0; i < 8; i++) {
        float inv = 1.f / lrow[i];
        float4 o = O4[i];
        o.x *= inv; o.y *= inv; o.z *= inv; o.w *= inv;
        *reinterpret_cast<float4*>(
            z + (size_t)(b * P_ + q0 + ty * 8 + i) * M_ + h * 64 + tx * 4) = o;
    }
}

// ---------------------------------------------------------------------------
extern "C" void kernel_launch(void* const* d_in, const int* in_sizes, int n_in,
                              void* d_out, int out_size)
{
    (void)in_sizes; (void)n_in; (void)out_size;
    const float* x      = (const float*)d_in[0];
    const float* W_attn = (const float*)d_in[1];
    const float* b_attn = (const float*)d_in[2];
    const float* W_proj = (const float*)d_in[3];
    const float* b_proj = (const float*)d_in[4];
    float* out = (float*)d_out;

    void* qkvp = nullptr;
    void* zp = nullptr;
    cudaGetSymbolAddress(&qkvp, g_qkv);
    cudaGetSymbolAddress(&zp, g_z);

    static bool attr_set = false;
    if (!attr_set) {
        cudaFuncSetAttribute(attn2_kernel,
                             cudaFuncAttributeMaxDynamicSharedMemorySize,
                             AT_SMEM_BYTES);
        attr_set = true;
    }

    dim3 blk(256);
    // QKV projection: [4096,1024] @ [1024,3072] + b_attn
    sgemm_bias_kernel<<<dim3(N3M_ / 128, ROWS_ / 128), blk>>>(
        x, W_attn, b_attn, (float*)qkvp, ROWS_, N3M_, M_);
    // causal attention per (b,h,q-tile of 128)
    attn2_kernel<<<dim3(P_ / 128, B_ * H_), blk, AT_SMEM_BYTES>>>(
        (const float*)qkvp, (float*)zp);
    // output projection: [4096,1024] @ [1024,1024] + b_proj
    sgemm_bias_kernel<<<dim3(M_ / 128, ROWS_ / 128), blk>>>(
        (const float*)zp, W_proj, b_proj, out, ROWS_, M_, M_);
}

// round 5
// speedup vs baseline: 2.9222x; 1.5258x over previous
#include <cuda_runtime.h>
#include <cuda_bf16.h>
#include <cstdint>

// Problem constants
#define B_ 2
#define P_ 2048
#define M_ 1024
#define H_ 16
#define D_ 64
#define ROWS_ (B_*P_)          // 4096
#define N3M_ (3*M_)            // 3072

// Scratch (allocation-free rule: __device__ globals)
__device__ float g_qkv[(size_t)ROWS_ * N3M_];   // [4096][3072]
__device__ float g_z[(size_t)ROWS_ * M_];       // [4096][1024]
// bf16 split planes (reused: x then z for A; W_attn then W_proj for B)
__device__ __nv_bfloat16 g_ah[(size_t)ROWS_ * M_];
__device__ __nv_bfloat16 g_al[(size_t)ROWS_ * M_];
__device__ __nv_bfloat16 g_bh[(size_t)M_ * N3M_];
__device__ __nv_bfloat16 g_bl[(size_t)M_ * N3M_];

// ---------------------------------------------------------------------------
// PTX helpers
// ---------------------------------------------------------------------------
__device__ __forceinline__ unsigned int smem_u32(const void* p) {
    return (unsigned int)__cvta_generic_to_shared(p);
}
__device__ __forceinline__ void ldm4(unsigned int* r, unsigned int a) {
    asm volatile("ldmatrix.sync.aligned.m8n8.x4.shared.b16 {%0,%1,%2,%3}, [%4];\n"
        : "=r"(r[0]), "=r"(r[1]), "=r"(r[2]), "=r"(r[3]) : "r"(a));
}
__device__ __forceinline__ void ldm4t(unsigned int* r, unsigned int a) {
    asm volatile("ldmatrix.sync.aligned.m8n8.x4.trans.shared.b16 {%0,%1,%2,%3}, [%4];\n"
        : "=r"(r[0]), "=r"(r[1]), "=r"(r[2]), "=r"(r[3]) : "r"(a));
}
__device__ __forceinline__ void mma16816(float* c, const unsigned int* a,
                                         unsigned int b0, unsigned int b1) {
    asm volatile(
        "mma.sync.aligned.m16n8k16.row.col.f32.bf16.bf16.f32 "
        "{%0,%1,%2,%3}, {%4,%5,%6,%7}, {%8,%9}, {%0,%1,%2,%3};\n"
        : "+f"(c[0]), "+f"(c[1]), "+f"(c[2]), "+f"(c[3])
        : "r"(a[0]), "r"(a[1]), "r"(a[2]), "r"(a[3]), "r"(b0), "r"(b1));
}

// ---------------------------------------------------------------------------
// Split fp32 -> (hi, lo) bf16 planes.  total elements multiple of 1024.
// ---------------------------------------------------------------------------
__global__ __launch_bounds__(256) void split_kernel(
    const float* __restrict__ in, __nv_bfloat16* __restrict__ hi,
    __nv_bfloat16* __restrict__ lo)
{
    int i = (blockIdx.x * 256 + threadIdx.x) * 4;
    float4 v = *reinterpret_cast<const float4*>(in + i);
    __nv_bfloat16 h0 = __float2bfloat16(v.x);
    __nv_bfloat16 h1 = __float2bfloat16(v.y);
    __nv_bfloat16 h2 = __float2bfloat16(v.z);
    __nv_bfloat16 h3 = __float2bfloat16(v.w);
    __nv_bfloat16 l0 = __float2bfloat16(v.x - __bfloat162float(h0));
    __nv_bfloat16 l1 = __float2bfloat16(v.y - __bfloat162float(h1));
    __nv_bfloat16 l2 = __float2bfloat16(v.z - __bfloat162float(h2));
    __nv_bfloat16 l3 = __float2bfloat16(v.w - __bfloat162float(h3));
    __nv_bfloat162 hp0, hp1, lp0, lp1;
    hp0.x = h0; hp0.y = h1; hp1.x = h2; hp1.y = h3;
    lp0.x = l0; lp0.y = l1; lp1.x = l2; lp1.y = l3;
    uint2 ho, lo2;
    ho.x = *(unsigned int*)&hp0; ho.y = *(unsigned int*)&hp1;
    lo2.x = *(unsigned int*)&lp0; lo2.y = *(unsigned int*)&lp1;
    *reinterpret_cast<uint2*>(hi + i) = ho;
    *reinterpret_cast<uint2*>(lo + i) = lo2;
}

// ---------------------------------------------------------------------------
// bf16x3 split-precision GEMM: C = A @ B + bias  (fp32-accurate)
// A[Mr][Kd] via (Ah,Al), B[Kd][Nc] via (Bh,Bl). BM=BN=128, BK=32.
// 256 threads = 8 warps in 2(m) x 4(n); each warp 64x32 via m16n8k16 MMAs.
// 3 MMAs per product: hi*hi + lo*hi + hi*lo.
// ---------------------------------------------------------------------------
#define ASTRIDE 40    // bf16 per A smem row (32 + 8 pad)
#define BSTRIDE 136   // bf16 per B smem row (128 + 8 pad)

__global__ __launch_bounds__(256) void gemm_bf16x3_kernel(
    const __nv_bfloat16* __restrict__ Ah, const __nv_bfloat16* __restrict__ Al,
    const __nv_bfloat16* __restrict__ Bh, const __nv_bfloat16* __restrict__ Bl,
    const float* __restrict__ bias, float* __restrict__ C,
    int Nc, int Kd)
{
    __shared__ __align__(16) __nv_bfloat16 sAh[128 * ASTRIDE];
    __shared__ __align__(16) __nv_bfloat16 sAl[128 * ASTRIDE];
    __shared__ __align__(16) __nv_bfloat16 sBh[32 * BSTRIDE];
    __shared__ __align__(16) __nv_bfloat16 sBl[32 * BSTRIDE];

    const int tid = threadIdx.x;
    const int lane = tid & 31;
    const int warp = tid >> 5;
    const int bm = blockIdx.y * 128;
    const int bn = blockIdx.x * 128;
    const int wm = (warp >> 2) * 64;   // warp m offset in tile
    const int wn = (warp & 3) * 32;    // warp n offset in tile

    // A global load mapping: 128 rows x 32 cols, 8 bf16 per thread per half
    const int ar = tid >> 2;           // 0..63 (A rows, +64 second half)
    const int as = (tid & 3) * 8;      // A col segment (8 bf16)
    // B global load mapping: 32 rows x 128 cols, 2 rows x 8 bf16 per thread
    const int br = tid >> 4;           // 0..15 (B rows, +16 second half)
    const int bc = (tid & 15) * 8;     // B col segment (8 bf16)

    const __nv_bfloat16* gAh = Ah + (size_t)(bm + ar) * Kd + as;
    const __nv_bfloat16* gAl = Al + (size_t)(bm + ar) * Kd + as;
    const __nv_bfloat16* gBh = Bh + (size_t)br * Nc + bn + bc;
    const __nv_bfloat16* gBl = Bl + (size_t)br * Nc + bn + bc;

    float acc[4][4][4];
#pragma unroll
    for (int i = 0; i < 4; i++)
#pragma unroll
        for (int j = 0; j < 4; j++)
#pragma unroll
            for (int k = 0; k < 4; k++) acc[i][j][k] = 0.f;

    // prefetch k-chunk 0
    uint4 rAh0 = *(const uint4*)(gAh);
    uint4 rAh1 = *(const uint4*)(gAh + (size_t)64 * Kd);
    uint4 rAl0 = *(const uint4*)(gAl);
    uint4 rAl1 = *(const uint4*)(gAl + (size_t)64 * Kd);
    uint4 rBh0 = *(const uint4*)(gBh);
    uint4 rBh1 = *(const uint4*)(gBh + (size_t)16 * Nc);
    uint4 rBl0 = *(const uint4*)(gBl);
    uint4 rBl1 = *(const uint4*)(gBl + (size_t)16 * Nc);

    const int l15 = lane & 15;
    const int l16 = lane >> 4;
    const int niter = Kd / 32;

    for (int it = 0; it < niter; ++it) {
        __syncthreads();
        *(uint4*)&sAh[ar * ASTRIDE + as] = rAh0;
        *(uint4*)&sAh[(ar + 64) * ASTRIDE + as] = rAh1;
        *(uint4*)&sAl[ar * ASTRIDE + as] = rAl0;
        *(uint4*)&sAl[(ar + 64) * ASTRIDE + as] = rAl1;
        *(uint4*)&sBh[br * BSTRIDE + bc] = rBh0;
        *(uint4*)&sBh[(br + 16) * BSTRIDE + bc] = rBh1;
        *(uint4*)&sBl[br * BSTRIDE + bc] = rBl0;
        *(uint4*)&sBl[(br + 16) * BSTRIDE + bc] = rBl1;
        __syncthreads();

        if (it + 1 < niter) {
            int k0 = (it + 1) * 32;
            rAh0 = *(const uint4*)(gAh + k0);
            rAh1 = *(const uint4*)(gAh + (size_t)64 * Kd + k0);
            rAl0 = *(const uint4*)(gAl + k0);
            rAl1 = *(const uint4*)(gAl + (size_t)64 * Kd + k0);
            rBh0 = *(const uint4*)(gBh + (size_t)k0 * Nc);
            rBh1 = *(const uint4*)(gBh + (size_t)(k0 + 16) * Nc);
            rBl0 = *(const uint4*)(gBl + (size_t)k0 * Nc);
            rBl1 = *(const uint4*)(gBl + (size_t)(k0 + 16) * Nc);
        }

#pragma unroll
        for (int ks = 0; ks < 2; ++ks) {
            unsigned int ah[4][4], al[4][4], bb[2][4];
#pragma unroll
            for (int mt = 0; mt < 4; ++mt)
                ldm4(ah[mt], smem_u32(
                    &sAh[(wm + mt * 16 + l15) * ASTRIDE + ks * 16 + l16 * 8]));
#pragma unroll
            for (int ng = 0; ng < 2; ++ng)
                ldm4t(bb[ng], smem_u32(
                    &sBh[(ks * 16 + l15) * BSTRIDE + wn + ng * 16 + l16 * 8]));
            // hi * hi
#pragma unroll
            for (int mt = 0; mt < 4; ++mt)
#pragma unroll
                for (int nt = 0; nt < 4; ++nt)
                    mma16816(acc[mt][nt], ah[mt],
                             bb[nt >> 1][(nt & 1) * 2], bb[nt >> 1][(nt & 1) * 2 + 1]);
            // lo * hi
#pragma unroll
            for (int mt = 0; mt < 4; ++mt)
                ldm4(al[mt], smem_u32(
                    &sAl[(wm + mt * 16 + l15) * ASTRIDE + ks * 16 + l16 * 8]));
#pragma unroll
            for (int mt = 0; mt < 4; ++mt)
#pragma unroll
                for (int nt = 0; nt < 4; ++nt)
                    mma16816(acc[mt][nt], al[mt],
                             bb[nt >> 1][(nt & 1) * 2], bb[nt >> 1][(nt & 1) * 2 + 1]);
            // hi * lo
#pragma unroll
            for (int ng = 0; ng < 2; ++ng)
                ldm4t(bb[ng], smem_u32(
                    &sBl[(ks * 16 + l15) * BSTRIDE + wn + ng * 16 + l16 * 8]));
#pragma unroll
            for (int mt = 0; mt < 4; ++mt)
#pragma unroll
                for (int nt = 0; nt < 4; ++nt)
                    mma16816(acc[mt][nt], ah[mt],
                             bb[nt >> 1][(nt & 1) * 2], bb[nt >> 1][(nt & 1) * 2 + 1]);
        }
    }

    // epilogue: c0=C[g][2t], c1=C[g][2t+1], c2=C[g+8][2t], c3=C[g+8][2t+1]
    const int g = lane >> 2;
    const int t2 = (lane & 3) * 2;
#pragma unroll
    for (int mt = 0; mt < 4; ++mt) {
        int row = bm + wm + mt * 16 + g;
#pragma unroll
        for (int nt = 0; nt < 4; ++nt) {
            int col = bn + wn + nt * 8 + t2;
            float b0 = __ldg(bias + col);
            float b1 = __ldg(bias + col + 1);
            float2 v0, v1;
            v0.x = acc[mt][nt][0] + b0; v0.y = acc[mt][nt][1] + b1;
            v1.x = acc[mt][nt][2] + b0; v1.y = acc[mt][nt][3] + b1;
            *reinterpret_cast<float2*>(C + (size_t)row * Nc + col) = v0;
            *reinterpret_cast<float2*>(C + (size_t)(row + 8) * Nc + col) = v1;
        }
    }
}

// ---------------------------------------------------------------------------
// Flash-style causal attention v2 (unchanged from R3).
// ---------------------------------------------------------------------------
#define AT_SMEM_FLOATS (64*132 + 64*132 + 128*132 + 128*68)
#define AT_SMEM_BYTES  (AT_SMEM_FLOATS * 4)

__global__ __launch_bounds__(256) void attn2_kernel(
    const float* __restrict__ qkv, float* __restrict__ z)
{
    extern __shared__ float sm[];
    float* Qt = sm;                       // [64][132]
    float* Kt = Qt + 64 * 132;            // [64][132]
    float* Ps = Kt + 64 * 132;            // [128][132]
    float* Vs = Ps + 128 * 132;           // [128][68]

    const int tid = threadIdx.x;
    const int bh = blockIdx.y;
    const int b = bh >> 4;
    const int h = bh & 15;
    const int qt = (int)gridDim.x - 1 - (int)blockIdx.x;
    const int q0 = qt * 128;

    const int ty = tid >> 4;
    const int tx = tid & 15;

    const float* qbase = qkv + (size_t)(b * P_ + q0) * N3M_ + h * 64;
#pragma unroll
    for (int l2 = 0; l2 < 8; l2++) {
        int fi = tid + l2 * 256;
        int row = fi >> 4;
        int d4 = fi & 15;
        float4 v = *reinterpret_cast<const float4*>(qbase + (size_t)row * N3M_ + d4 * 4);
        Qt[(d4 * 4 + 0) * 132 + row] = v.x * 0.125f;
        Qt[(d4 * 4 + 1) * 132 + row] = v.y * 0.125f;
        Qt[(d4 * 4 + 2) * 132 + row] = v.z * 0.125f;
        Qt[(d4 * 4 + 3) * 132 + row] = v.w * 0.125f;
    }

    float4 O4[8];
#pragma unroll
    for (int i = 0; i < 8; i++) O4[i] = make_float4(0.f, 0.f, 0.f, 0.f);
    float mrow[8], lrow[8];
#pragma unroll
    for (int i = 0; i < 8; i++) { mrow[i] = -1e30f; lrow[i] = 0.f; }

    for (int kt = 0; kt <= qt; ++kt) {
        const int k0 = kt * 128;
        const float* kbase = qkv + (size_t)(b * P_ + k0) * N3M_ + M_ + h * 64;
        const float* vbase = qkv + (size_t)(b * P_ + k0) * N3M_ + 2 * M_ + h * 64;

#pragma unroll
        for (int l2 = 0; l2 < 8; l2++) {
            int fi = tid + l2 * 256;
            int row = fi >> 4;
            int d4 = fi & 15;
            float4 kv = *reinterpret_cast<const float4*>(kbase + (size_t)row * N3M_ + d4 * 4);
            Kt[(d4 * 4 + 0) * 132 + row] = kv.x;
            Kt[(d4 * 4 + 1) * 132 + row] = kv.y;
            Kt[(d4 * 4 + 2) * 132 + row] = kv.z;
            Kt[(d4 * 4 + 3) * 132 + row] = kv.w;
            float4 vv = *reinterpret_cast<const float4*>(vbase + (size_t)row * N3M_ + d4 * 4);
            *reinterpret_cast<float4*>(Vs + row * 68 + d4 * 4) = vv;
        }
        __syncthreads();

        float s[8][8];
#pragma unroll
        for (int i = 0; i < 8; i++)
#pragma unroll
            for (int j = 0; j < 8; j++) s[i][j] = 0.f;

#pragma unroll 4
        for (int d = 0; d < 64; d++) {
            float4 a0 = *reinterpret_cast<const float4*>(Qt + d * 132 + ty * 8);
            float4 a1 = *reinterpret_cast<const float4*>(Qt + d * 132 + ty * 8 + 4);
            float4 b0 = *reinterpret_cast<const float4*>(Kt + d * 132 + tx * 8);
            float4 b1 = *reinterpret_cast<const float4*>(Kt + d * 132 + tx * 8 + 4);
            float ra[8] = {a0.x, a0.y, a0.z, a0.w, a1.x, a1.y, a1.z, a1.w};
            float rb[8] = {b0.x, b0.y, b0.z, b0.w, b1.x, b1.y, b1.z, b1.w};
#pragma unroll
            for (int i = 0; i < 8; i++)
#pragma unroll
                for (int j = 0; j < 8; j++)
                    s[i][j] += ra[i] * rb[j];
        }

        if (kt == qt) {
#pragma unroll
            for (int i = 0; i < 8; i++)
#pragma unroll
                for (int j = 0; j < 8; j++)
                    if (tx * 8 + j > ty * 8 + i) s[i][j] = -1e30f;
        }

#pragma unroll
        for (int i = 0; i < 8; i++) {
            float mx = s[i][0];
#pragma unroll
            for (int j = 1; j < 8; j++) mx = fmaxf(mx, s[i][j]);
            mx = fmaxf(mx, __shfl_xor_sync(0xffffffffu, mx, 1));
            mx = fmaxf(mx, __shfl_xor_sync(0xffffffffu, mx, 2));
            mx = fmaxf(mx, __shfl_xor_sync(0xffffffffu, mx, 4));
            mx = fmaxf(mx, __shfl_xor_sync(0xffffffffu, mx, 8));
            float mnew = fmaxf(mrow[i], mx);
            float corr = __expf(mrow[i] - mnew);
            mrow[i] = mnew;
            float sum = 0.f;
#pragma unroll
            for (int j = 0; j < 8; j++) {
                s[i][j] = __expf(s[i][j] - mnew);
                sum += s[i][j];
            }
            sum += __shfl_xor_sync(0xffffffffu, sum, 1);
            sum += __shfl_xor_sync(0xffffffffu, sum, 2);
            sum += __shfl_xor_sync(0xffffffffu, sum, 4);
            sum += __shfl_xor_sync(0xffffffffu, sum, 8);
            lrow[i] = lrow[i] * corr + sum;
            O4[i].x *= corr; O4[i].y *= corr;
            O4[i].z *= corr; O4[i].w *= corr;
        }

#pragma unroll
        for (int i = 0; i < 8; i++) {
            *reinterpret_cast<float4*>(Ps + (ty * 8 + i) * 132 + tx * 8) =
                make_float4(s[i][0], s[i][1], s[i][2], s[i][3]);
            *reinterpret_cast<float4*>(Ps + (ty * 8 + i) * 132 + tx * 8 + 4) =
                make_float4(s[i][4], s[i][5], s[i][6], s[i][7]);
        }
        __syncthreads();

#pragma unroll 2
        for (int k = 0; k < 128; k += 4) {
            float4 vv0 = *reinterpret_cast<const float4*>(Vs + (k + 0) * 68 + tx * 4);
            float4 vv1 = *reinterpret_cast<const float4*>(Vs + (k + 1) * 68 + tx * 4);
            float4 vv2 = *reinterpret_cast<const float4*>(Vs + (k + 2) * 68 + tx * 4);
            float4 vv3 = *reinterpret_cast<const float4*>(Vs + (k + 3) * 68 + tx * 4);
#pragma unroll
            for (int i = 0; i < 8; i++) {
                float4 pp = *reinterpret_cast<const float4*>(Ps + (ty * 8 + i) * 132 + k);
                O4[i].x += pp.x * vv0.x + pp.y * vv1.x + pp.z * vv2.x + pp.w * vv3.x;
                O4[i].y += pp.x * vv0.y + pp.y * vv1.y + pp.z * vv2.y + pp.w * vv3.y;
                O4[i].z += pp.x * vv0.z + pp.y * vv1.z + pp.z * vv2.z + pp.w * vv3.z;
                O4[i].w += pp.x * vv0.w + pp.y * vv1.w + pp.z * vv2.w + pp.w * vv3.w;
            }
        }
        __syncthreads();
    }

#pragma unroll
    for (int i = 0; i < 8; i++) {
        float inv = 1.f / lrow[i];
        float4 o = O4[i];
        o.x *= inv; o.y *= inv; o.z *= inv; o.w *= inv;
        *reinterpret_cast<float4*>(
            z + (size_t)(b * P_ + q0 + ty * 8 + i) * M_ + h * 64 + tx * 4) = o;
    }
}

// ---------------------------------------------------------------------------
extern "C" void kernel_launch(void* const* d_in, const int* in_sizes, int n_in,
                              void* d_out, int out_size)
{
    (void)in_sizes; (void)n_in; (void)out_size;
    const float* x      = (const float*)d_in[0];
    const float* W_attn = (const float*)d_in[1];
    const float* b_attn = (const float*)d_in[2];
    const float* W_proj = (const float*)d_in[3];
    const float* b_proj = (const float*)d_in[4];
    float* out = (float*)d_out;

    void* qkvp = 0;
    void* zp = 0;
    void* ahp = 0;
    void* alp = 0;
    void* bhp = 0;
    void* blp = 0;
    cudaGetSymbolAddress(&qkvp, g_qkv);
    cudaGetSymbolAddress(&zp, g_z);
    cudaGetSymbolAddress(&ahp, g_ah);
    cudaGetSymbolAddress(&alp, g_al);
    cudaGetSymbolAddress(&bhp, g_bh);
    cudaGetSymbolAddress(&blp, g_bl);

    cudaFuncSetAttribute(attn2_kernel,
                         cudaFuncAttributeMaxDynamicSharedMemorySize,
                         AT_SMEM_BYTES);

    dim3 blk(256);

    // split x and W_attn into bf16 hi/lo planes
    split_kernel<<<(ROWS_ * M_) / 1024, blk>>>(
        x, (__nv_bfloat16*)ahp, (__nv_bfloat16*)alp);
    split_kernel<<<(M_ * N3M_) / 1024, blk>>>(
        W_attn, (__nv_bfloat16*)bhp, (__nv_bfloat16*)blp);

    // QKV projection on tensor cores
    gemm_bf16x3_kernel<<<dim3(N3M_ / 128, ROWS_ / 128), blk>>>(
        (const __nv_bfloat16*)ahp, (const __nv_bfloat16*)alp,
        (const __nv_bfloat16*)bhp, (const __nv_bfloat16*)blp,
        b_attn, (float*)qkvp, N3M_, M_);

    // causal attention
    attn2_kernel<<<dim3(P_ / 128, B_ * H_), blk, AT_SMEM_BYTES>>>(
        (const float*)qkvp, (float*)zp);

    // split z and W_proj (reuse planes)
    split_kernel<<<(ROWS_ * M_) / 1024, blk>>>(
        (const float*)zp, (__nv_bfloat16*)ahp, (__nv_bfloat16*)alp);
    split_kernel<<<(M_ * M_) / 1024, blk>>>(
        W_proj, (__nv_bfloat16*)bhp, (__nv_bfloat16*)blp);

    // output projection on tensor cores
    gemm_bf16x3_kernel<<<dim3(M_ / 128, ROWS_ / 128), blk>>>(
        (const __nv_bfloat16*)ahp, (const __nv_bfloat16*)alp,
        (const __nv_bfloat16*)bhp, (const __nv_bfloat16*)blp,
        b_proj, out, M_, M_);
}

// round 6
// speedup vs baseline: 5.0336x; 1.7226x over previous
#include <cuda_runtime.h>
#include <cuda_bf16.h>
#include <cstdint>

// Problem constants
#define B_ 2
#define P_ 2048
#define M_ 1024
#define H_ 16
#define D_ 64
#define ROWS_ (B_*P_)          // 4096
#define N3M_ (3*M_)            // 3072

// Scratch (allocation-free rule: __device__ globals)
__device__ __nv_bfloat16 g_qkvh[(size_t)ROWS_ * N3M_];  // qkv hi plane (Q pre-scaled)
__device__ __nv_bfloat16 g_qkvl[(size_t)ROWS_ * N3M_];  // qkv lo plane
__device__ __nv_bfloat16 g_ah[(size_t)ROWS_ * M_];      // A planes: x, then z
__device__ __nv_bfloat16 g_al[(size_t)ROWS_ * M_];
__device__ __nv_bfloat16 g_bh[(size_t)M_ * N3M_];       // B planes: W_attn, then W_proj
__device__ __nv_bfloat16 g_bl[(size_t)M_ * N3M_];

// ---------------------------------------------------------------------------
// PTX helpers
// ---------------------------------------------------------------------------
__device__ __forceinline__ unsigned int smem_u32(const void* p) {
    return (unsigned int)__cvta_generic_to_shared(p);
}
__device__ __forceinline__ void ldm4(unsigned int* r, unsigned int a) {
    asm volatile("ldmatrix.sync.aligned.m8n8.x4.shared.b16 {%0,%1,%2,%3}, [%4];\n"
        : "=r"(r[0]), "=r"(r[1]), "=r"(r[2]), "=r"(r[3]) : "r"(a));
}
__device__ __forceinline__ void ldm4t(unsigned int* r, unsigned int a) {
    asm volatile("ldmatrix.sync.aligned.m8n8.x4.trans.shared.b16 {%0,%1,%2,%3}, [%4];\n"
        : "=r"(r[0]), "=r"(r[1]), "=r"(r[2]), "=r"(r[3]) : "r"(a));
}
__device__ __forceinline__ void mma16816(float* c, const unsigned int* a,
                                         unsigned int b0, unsigned int b1) {
    asm volatile(
        "mma.sync.aligned.m16n8k16.row.col.f32.bf16.bf16.f32 "
        "{%0,%1,%2,%3}, {%4,%5,%6,%7}, {%8,%9}, {%0,%1,%2,%3};\n"
        : "+f"(c[0]), "+f"(c[1]), "+f"(c[2]), "+f"(c[3])
        : "r"(a[0]), "r"(a[1]), "r"(a[2]), "r"(a[3]), "r"(b0), "r"(b1));
}
__device__ __forceinline__ void cp_cg16(unsigned int d, const void* s) {
    asm volatile("cp.async.cg.shared.global [%0], [%1], 16;\n" :: "r"(d), "l"(s));
}
// pack (even, odd) floats into bf16x2 (odd -> high half)
__device__ __forceinline__ unsigned int packbf(float e, float o) {
    unsigned int r;
    asm("cvt.rn.bf16x2.f32 %0, %1, %2;\n" : "=r"(r) : "f"(o), "f"(e));
    return r;
}
__device__ __forceinline__ float blo(unsigned int u) { return __uint_as_float(u << 16); }
__device__ __forceinline__ float bhi(unsigned int u) { return __uint_as_float(u & 0xffff0000u); }

// ---------------------------------------------------------------------------
// Split fp32 -> (hi, lo) bf16 planes.
// ---------------------------------------------------------------------------
__global__ __launch_bounds__(256) void split_kernel(
    const float* __restrict__ in, __nv_bfloat16* __restrict__ hi,
    __nv_bfloat16* __restrict__ lo)
{
    int i = (blockIdx.x * 256 + threadIdx.x) * 4;
    float4 v = *reinterpret_cast<const float4*>(in + i);
    unsigned int h0 = packbf(v.x, v.y);
    unsigned int h1 = packbf(v.z, v.w);
    unsigned int l0 = packbf(v.x - blo(h0), v.y - bhi(h0));
    unsigned int l1 = packbf(v.z - blo(h1), v.w - bhi(h1));
    uint2 ho, lo2;
    ho.x = h0; ho.y = h1; lo2.x = l0; lo2.y = l1;
    *reinterpret_cast<uint2*>(hi + i) = ho;
    *reinterpret_cast<uint2*>(lo + i) = lo2;
}

// ---------------------------------------------------------------------------
// bf16x3 split-precision GEMM core. Two epilogues:
//   gemm_bf16x3_kernel:  fp32 C = A@B + bias
//   gemm_qkv_kernel:     bf16 hi/lo C planes, cols < 1024 scaled by 0.125 (Q)
// ---------------------------------------------------------------------------
#define ASTRIDE 40
#define BSTRIDE 136

struct GemmFrag { float acc[4][4][4]; int bm, bn; int lane, warp; };

template <int EPI>   // 0 = fp32+bias, 1 = qkv bf16 hi/lo
__global__ __launch_bounds__(256) void gemm_bf16x3_t(
    const __nv_bfloat16* __restrict__ Ah, const __nv_bfloat16* __restrict__ Al,
    const __nv_bfloat16* __restrict__ Bh, const __nv_bfloat16* __restrict__ Bl,
    const float* __restrict__ bias, float* __restrict__ C,
    __nv_bfloat16* __restrict__ Ch, __nv_bfloat16* __restrict__ Cl,
    int Nc, int Kd)
{
    __shared__ __align__(16) __nv_bfloat16 sAh[128 * ASTRIDE];
    __shared__ __align__(16) __nv_bfloat16 sAl[128 * ASTRIDE];
    __shared__ __align__(16) __nv_bfloat16 sBh[32 * BSTRIDE];
    __shared__ __align__(16) __nv_bfloat16 sBl[32 * BSTRIDE];

    const int tid = threadIdx.x;
    const int lane = tid & 31;
    const int warp = tid >> 5;
    const int bm = blockIdx.y * 128;
    const int bn = blockIdx.x * 128;
    const int wm = (warp >> 2) * 64;
    const int wn = (warp & 3) * 32;

    const int ar = tid >> 2;
    const int as = (tid & 3) * 8;
    const int br = tid >> 4;
    const int bc = (tid & 15) * 8;

    const __nv_bfloat16* gAh = Ah + (size_t)(bm + ar) * Kd + as;
    const __nv_bfloat16* gAl = Al + (size_t)(bm + ar) * Kd + as;
    const __nv_bfloat16* gBh = Bh + (size_t)br * Nc + bn + bc;
    const __nv_bfloat16* gBl = Bl + (size_t)br * Nc + bn + bc;

    float acc[4][4][4];
#pragma unroll
    for (int i = 0; i < 4; i++)
#pragma unroll
        for (int j = 0; j < 4; j++)
#pragma unroll
            for (int k = 0; k < 4; k++) acc[i][j][k] = 0.f;

    uint4 rAh0 = *(const uint4*)(gAh);
    uint4 rAh1 = *(const uint4*)(gAh + (size_t)64 * Kd);
    uint4 rAl0 = *(const uint4*)(gAl);
    uint4 rAl1 = *(const uint4*)(gAl + (size_t)64 * Kd);
    uint4 rBh0 = *(const uint4*)(gBh);
    uint4 rBh1 = *(const uint4*)(gBh + (size_t)16 * Nc);
    uint4 rBl0 = *(const uint4*)(gBl);
    uint4 rBl1 = *(const uint4*)(gBl + (size_t)16 * Nc);

    const int l15 = lane & 15;
    const int l16 = lane >> 4;
    const int niter = Kd / 32;

    for (int it = 0; it < niter; ++it) {
        __syncthreads();
        *(uint4*)&sAh[ar * ASTRIDE + as] = rAh0;
        *(uint4*)&sAh[(ar + 64) * ASTRIDE + as] = rAh1;
        *(uint4*)&sAl[ar * ASTRIDE + as] = rAl0;
        *(uint4*)&sAl[(ar + 64) * ASTRIDE + as] = rAl1;
        *(uint4*)&sBh[br * BSTRIDE + bc] = rBh0;
        *(uint4*)&sBh[(br + 16) * BSTRIDE + bc] = rBh1;
        *(uint4*)&sBl[br * BSTRIDE + bc] = rBl0;
        *(uint4*)&sBl[(br + 16) * BSTRIDE + bc] = rBl1;
        __syncthreads();

        if (it + 1 < niter) {
            int k0 = (it + 1) * 32;
            rAh0 = *(const uint4*)(gAh + k0);
            rAh1 = *(const uint4*)(gAh + (size_t)64 * Kd + k0);
            rAl0 = *(const uint4*)(gAl + k0);
            rAl1 = *(const uint4*)(gAl + (size_t)64 * Kd + k0);
            rBh0 = *(const uint4*)(gBh + (size_t)k0 * Nc);
            rBh1 = *(const uint4*)(gBh + (size_t)(k0 + 16) * Nc);
            rBl0 = *(const uint4*)(gBl + (size_t)k0 * Nc);
            rBl1 = *(const uint4*)(gBl + (size_t)(k0 + 16) * Nc);
        }

#pragma unroll
        for (int ks = 0; ks < 2; ++ks) {
            unsigned int ah[4][4], al[4][4], bb[2][4];
#pragma unroll
            for (int mt = 0; mt < 4; ++mt)
                ldm4(ah[mt], smem_u32(
                    &sAh[(wm + mt * 16 + l15) * ASTRIDE + ks * 16 + l16 * 8]));
#pragma unroll
            for (int ng = 0; ng < 2; ++ng)
                ldm4t(bb[ng], smem_u32(
                    &sBh[(ks * 16 + l15) * BSTRIDE + wn + ng * 16 + l16 * 8]));
#pragma unroll
            for (int mt = 0; mt < 4; ++mt)
#pragma unroll
                for (int nt = 0; nt < 4; ++nt)
                    mma16816(acc[mt][nt], ah[mt],
                             bb[nt >> 1][(nt & 1) * 2], bb[nt >> 1][(nt & 1) * 2 + 1]);
#pragma unroll
            for (int mt = 0; mt < 4; ++mt)
                ldm4(al[mt], smem_u32(
                    &sAl[(wm + mt * 16 + l15) * ASTRIDE + ks * 16 + l16 * 8]));
#pragma unroll
            for (int mt = 0; mt < 4; ++mt)
#pragma unroll
                for (int nt = 0; nt < 4; ++nt)
                    mma16816(acc[mt][nt], al[mt],
                             bb[nt >> 1][(nt & 1) * 2], bb[nt >> 1][(nt & 1) * 2 + 1]);
#pragma unroll
            for (int ng = 0; ng < 2; ++ng)
                ldm4t(bb[ng], smem_u32(
                    &sBl[(ks * 16 + l15) * BSTRIDE + wn + ng * 16 + l16 * 8]));
#pragma unroll
            for (int mt = 0; mt < 4; ++mt)
#pragma unroll
                for (int nt = 0; nt < 4; ++nt)
                    mma16816(acc[mt][nt], ah[mt],
                             bb[nt >> 1][(nt & 1) * 2], bb[nt >> 1][(nt & 1) * 2 + 1]);
        }
    }

    const int g = lane >> 2;
    const int t2 = (lane & 3) * 2;
#pragma unroll
    for (int mt = 0; mt < 4; ++mt) {
        int row = bm + wm + mt * 16 + g;
#pragma unroll
        for (int nt = 0; nt < 4; ++nt) {
            int col = bn + wn + nt * 8 + t2;
            float b0 = __ldg(bias + col);
            float b1 = __ldg(bias + col + 1);
            float v00 = acc[mt][nt][0] + b0, v01 = acc[mt][nt][1] + b1;
            float v10 = acc[mt][nt][2] + b0, v11 = acc[mt][nt][3] + b1;
            if (EPI == 0) {
                float2 v0, v1;
                v0.x = v00; v0.y = v01; v1.x = v10; v1.y = v11;
                *reinterpret_cast<float2*>(C + (size_t)row * Nc + col) = v0;
                *reinterpret_cast<float2*>(C + (size_t)(row + 8) * Nc + col) = v1;
            } else {
                if (col < M_) { v00 *= 0.125f; v01 *= 0.125f; v10 *= 0.125f; v11 *= 0.125f; }
                unsigned int h0 = packbf(v00, v01);
                unsigned int h1 = packbf(v10, v11);
                unsigned int l0 = packbf(v00 - blo(h0), v01 - bhi(h0));
                unsigned int l1 = packbf(v10 - blo(h1), v11 - bhi(h1));
                *reinterpret_cast<unsigned int*>(Ch + (size_t)row * Nc + col) = h0;
                *reinterpret_cast<unsigned int*>(Ch + (size_t)(row + 8) * Nc + col) = h1;
                *reinterpret_cast<unsigned int*>(Cl + (size_t)row * Nc + col) = l0;
                *reinterpret_cast<unsigned int*>(Cl + (size_t)(row + 8) * Nc + col) = l1;
            }
        }
    }
}

// ---------------------------------------------------------------------------
// Tensor-core causal flash attention. One CTA = (b, h, 128-q-tile); 8 warps,
// each warp owns 16 q-rows x 128 keys (16 n-groups). bf16x3 split precision.
// K/V tiles double-buffered via cp.async. Writes z hi/lo planes.
// ---------------------------------------------------------------------------
#define KVS 72                     // bf16 per smem row (64 + 8 pad)
#define KVOFF(st, pl) (((st) * 4 + (pl)) * 128 * KVS)
#define QH_OFF (8 * 128 * KVS)     // 73728
#define QL_OFF (QH_OFF + 128 * KVS)
#define AT3_SMEM_BF16 (QL_OFF + 128 * KVS)
#define AT3_SMEM_BYTES (AT3_SMEM_BF16 * 2)   // 184320

__global__ __launch_bounds__(256, 1) void attn3_kernel(
    const __nv_bfloat16* __restrict__ qkvh, const __nv_bfloat16* __restrict__ qkvl,
    __nv_bfloat16* __restrict__ zh, __nv_bfloat16* __restrict__ zl)
{
    extern __shared__ __align__(16) __nv_bfloat16 sm3[];
    const unsigned int sbase = smem_u32(sm3);

    const int tid = threadIdx.x;
    const int lane = tid & 31;
    const int warp = tid >> 5;
    const int l15 = lane & 15;
    const int l16 = lane >> 4;
    const int bh = blockIdx.y;
    const int b = bh >> 4;
    const int h = bh & 15;
    const int qt = (int)gridDim.x - 1 - (int)blockIdx.x;   // heavy tiles first
    const int q0 = qt * 128;

    // --- issue Q tile cp.async (hi+lo), then K/V stage 0; one commit group ---
    {
        const size_t qrow = (size_t)(b * P_ + q0) * N3M_ + h * 64;
#pragma unroll
        for (int pq = 0; pq < 2; pq++) {
            const __nv_bfloat16* src = (pq ? qkvl : qkvh) + qrow;
            unsigned int sb = sbase + (pq ? QL_OFF : QH_OFF) * 2;
#pragma unroll
            for (int j = 0; j < 4; j++) {
                int si = tid + j * 256;
                int row = si >> 3, seg = si & 7;
                cp_cg16(sb + (row * KVS + seg * 8) * 2,
                        src + (size_t)row * N3M_ + seg * 8);
            }
        }
    }
    {
        const size_t rb = (size_t)(b * P_) * N3M_ + h * 64;   // ktile 0
        const __nv_bfloat16* pb[4];
        pb[0] = qkvh + rb + M_;  pb[1] = qkvl + rb + M_;
        pb[2] = qkvh + rb + 2 * M_;  pb[3] = qkvl + rb + 2 * M_;
#pragma unroll
        for (int p = 0; p < 4; p++) {
            unsigned int sb = sbase + KVOFF(0, p) * 2;
#pragma unroll
            for (int j = 0; j < 4; j++) {
                int si = tid + j * 256;
                int row = si >> 3, seg = si & 7;
                cp_cg16(sb + (row * KVS + seg * 8) * 2,
                        pb[p] + (size_t)row * N3M_ + seg * 8);
            }
        }
    }
    asm volatile("cp.async.commit_group;\n" ::: "memory");

    unsigned int fqh[4][4], fql[4][4];
    float oacc[8][4];
#pragma unroll
    for (int i = 0; i < 8; i++)
#pragma unroll
        for (int j = 0; j < 4; j++) oacc[i][j] = 0.f;
    float m0 = -1e30f, m1 = -1e30f, lr0 = 0.f, lr1 = 0.f;

    const unsigned int krow = (lane & 7) + ((lane >> 4) << 3);   // bcol-B row sel
    const unsigned int kcolb = ((lane >> 3) & 1) << 3;           // bcol-B col sel

    for (int kt = 0; kt <= qt; ++kt) {
        const int buf = kt & 1;
        if (kt < qt) {   // prefetch next stage
            const size_t rb = (size_t)(b * P_ + (kt + 1) * 128) * N3M_ + h * 64;
            const __nv_bfloat16* pb[4];
            pb[0] = qkvh + rb + M_;  pb[1] = qkvl + rb + M_;
            pb[2] = qkvh + rb + 2 * M_;  pb[3] = qkvl + rb + 2 * M_;
            const int st = (kt + 1) & 1;
#pragma unroll
            for (int p = 0; p < 4; p++) {
                unsigned int sb = sbase + KVOFF(st, p) * 2;
#pragma unroll
                for (int j = 0; j < 4; j++) {
                    int si = tid + j * 256;
                    int row = si >> 3, seg = si & 7;
                    cp_cg16(sb + (row * KVS + seg * 8) * 2,
                            pb[p] + (size_t)row * N3M_ + seg * 8);
                }
            }
            asm volatile("cp.async.commit_group;\n" ::: "memory");
            asm volatile("cp.async.wait_group 1;\n" ::: "memory");
        } else {
            asm volatile("cp.async.wait_group 0;\n" ::: "memory");
        }
        __syncthreads();

        if (kt == 0) {   // Q fragments (persistent)
#pragma unroll
            for (int ks = 0; ks < 4; ks++) {
                ldm4(fqh[ks], sbase +
                     (QH_OFF + (warp * 16 + l15) * KVS + ks * 16 + l16 * 8) * 2);
                ldm4(fql[ks], sbase +
                     (QL_OFF + (warp * 16 + l15) * KVS + ks * 16 + l16 * 8) * 2);
            }
        }

        // ---- S = Q K^T (bf16x3) ----
        float sacc[16][4];
#pragma unroll
        for (int g = 0; g < 16; g++)
#pragma unroll
            for (int e = 0; e < 4; e++) sacc[g][e] = 0.f;

        const unsigned int bKh = sbase + KVOFF(buf, 0) * 2;
        const unsigned int bKl = sbase + KVOFF(buf, 1) * 2;
#pragma unroll
        for (int ks = 0; ks < 4; ks++) {
            unsigned int kb[8][4];
#pragma unroll
            for (int gp = 0; gp < 8; gp++)
                ldm4(kb[gp], bKh + ((gp * 16 + krow) * KVS + ks * 16 + kcolb) * 2);
#pragma unroll
            for (int g = 0; g < 16; g++)
                mma16816(sacc[g], fqh[ks], kb[g >> 1][(g & 1) * 2], kb[g >> 1][(g & 1) * 2 + 1]);
#pragma unroll
            for (int g = 0; g < 16; g++)
                mma16816(sacc[g], fql[ks], kb[g >> 1][(g & 1) * 2], kb[g >> 1][(g & 1) * 2 + 1]);
#pragma unroll
            for (int gp = 0; gp < 8; gp++)
                ldm4(kb[gp], bKl + ((gp * 16 + krow) * KVS + ks * 16 + kcolb) * 2);
#pragma unroll
            for (int g = 0; g < 16; g++)
                mma16816(sacc[g], fqh[ks], kb[g >> 1][(g & 1) * 2], kb[g >> 1][(g & 1) * 2 + 1]);
        }

        // ---- causal mask on diagonal tile ----
        if (kt == qt) {
            const int r0l = warp * 16 + (lane >> 2);
#pragma unroll
            for (int g = 0; g < 16; g++) {
                int c0 = g * 8 + 2 * (lane & 3);
                if (c0 > r0l)     sacc[g][0] = -1e30f;
                if (c0 + 1 > r0l) sacc[g][1] = -1e30f;
                if (c0 > r0l + 8)     sacc[g][2] = -1e30f;
                if (c0 + 1 > r0l + 8) sacc[g][3] = -1e30f;
            }
        }

        // ---- online softmax (rows fully within quad: shfl xor 1,2) ----
        float mx0 = -1e30f, mx1 = -1e30f;
#pragma unroll
        for (int g = 0; g < 16; g++) {
            mx0 = fmaxf(mx0, fmaxf(sacc[g][0], sacc[g][1]));
            mx1 = fmaxf(mx1, fmaxf(sacc[g][2], sacc[g][3]));
        }
        mx0 = fmaxf(mx0, __shfl_xor_sync(0xffffffffu, mx0, 1));
        mx0 = fmaxf(mx0, __shfl_xor_sync(0xffffffffu, mx0, 2));
        mx1 = fmaxf(mx1, __shfl_xor_sync(0xffffffffu, mx1, 1));
        mx1 = fmaxf(mx1, __shfl_xor_sync(0xffffffffu, mx1, 2));
        float mn0 = fmaxf(m0, mx0), mn1 = fmaxf(m1, mx1);
        float cr0 = __expf(m0 - mn0), cr1 = __expf(m1 - mn1);
        m0 = mn0; m1 = mn1;
        float s0 = 0.f, s1 = 0.f;
#pragma unroll
        for (int g = 0; g < 16; g++) {
            sacc[g][0] = __expf(sacc[g][0] - m0); s0 += sacc[g][0];
            sacc[g][1] = __expf(sacc[g][1] - m0); s0 += sacc[g][1];
            sacc[g][2] = __expf(sacc[g][2] - m1); s1 += sacc[g][2];
            sacc[g][3] = __expf(sacc[g][3] - m1); s1 += sacc[g][3];
        }
        s0 += __shfl_xor_sync(0xffffffffu, s0, 1);
        s0 += __shfl_xor_sync(0xffffffffu, s0, 2);
        s1 += __shfl_xor_sync(0xffffffffu, s1, 1);
        s1 += __shfl_xor_sync(0xffffffffu, s1, 2);
        lr0 = lr0 * cr0 + s0;
        lr1 = lr1 * cr1 + s1;
#pragma unroll
        for (int g = 0; g < 8; g++) {
            oacc[g][0] *= cr0; oacc[g][1] *= cr0;
            oacc[g][2] *= cr1; oacc[g][3] *= cr1;
        }

        // ---- O += P V (bf16x3, P passed in registers) ----
        const unsigned int bVh = sbase + KVOFF(buf, 2) * 2;
        const unsigned int bVl = sbase + KVOFF(buf, 3) * 2;
#pragma unroll
        for (int s = 0; s < 8; s++) {
            unsigned int aph[4], apl[4];
            aph[0] = packbf(sacc[2*s][0], sacc[2*s][1]);
            aph[1] = packbf(sacc[2*s][2], sacc[2*s][3]);
            aph[2] = packbf(sacc[2*s+1][0], sacc[2*s+1][1]);
            aph[3] = packbf(sacc[2*s+1][2], sacc[2*s+1][3]);
            apl[0] = packbf(sacc[2*s][0] - blo(aph[0]), sacc[2*s][1] - bhi(aph[0]));
            apl[1] = packbf(sacc[2*s][2] - blo(aph[1]), sacc[2*s][3] - bhi(aph[1]));
            apl[2] = packbf(sacc[2*s+1][0] - blo(aph[2]), sacc[2*s+1][1] - bhi(aph[2]));
            apl[3] = packbf(sacc[2*s+1][2] - blo(aph[3]), sacc[2*s+1][3] - bhi(aph[3]));
            unsigned int vb[4][4];
#pragma unroll
            for (int n2 = 0; n2 < 4; n2++)
                ldm4t(vb[n2], bVh + ((s * 16 + l15) * KVS + n2 * 16 + l16 * 8) * 2);
#pragma unroll
            for (int g = 0; g < 8; g++)
                mma16816(oacc[g], aph, vb[g >> 1][(g & 1) * 2], vb[g >> 1][(g & 1) * 2 + 1]);
#pragma unroll
            for (int g = 0; g < 8; g++)
                mma16816(oacc[g], apl, vb[g >> 1][(g & 1) * 2], vb[g >> 1][(g & 1) * 2 + 1]);
#pragma unroll
            for (int n2 = 0; n2 < 4; n2++)
                ldm4t(vb[n2], bVl + ((s * 16 + l15) * KVS + n2 * 16 + l16 * 8) * 2);
#pragma unroll
            for (int g = 0; g < 8; g++)
                mma16816(oacc[g], aph, vb[g >> 1][(g & 1) * 2], vb[g >> 1][(g & 1) * 2 + 1]);
        }
        __syncthreads();
    }

    // ---- normalize, split and write z hi/lo ----
    const float inv0 = 1.f / lr0, inv1 = 1.f / lr1;
    const int r0 = b * P_ + q0 + warp * 16 + (lane >> 2);
    const int col0 = h * 64 + 2 * (lane & 3);
#pragma unroll
    for (int g = 0; g < 8; g++) {
        int col = col0 + g * 8;
        float f00 = oacc[g][0] * inv0, f01 = oacc[g][1] * inv0;
        float f10 = oacc[g][2] * inv1, f11 = oacc[g][3] * inv1;
        unsigned int h0 = packbf(f00, f01);
        unsigned int h1 = packbf(f10, f11);
        unsigned int l0 = packbf(f00 - blo(h0), f01 - bhi(h0));
        unsigned int l1 = packbf(f10 - blo(h1), f11 - bhi(h1));
        *reinterpret_cast<unsigned int*>(zh + (size_t)r0 * M_ + col) = h0;
        *reinterpret_cast<unsigned int*>(zl + (size_t)r0 * M_ + col) = l0;
        *reinterpret_cast<unsigned int*>(zh + (size_t)(r0 + 8) * M_ + col) = h1;
        *reinterpret_cast<unsigned int*>(zl + (size_t)(r0 + 8) * M_ + col) = l1;
    }
}

// ---------------------------------------------------------------------------
extern "C" void kernel_launch(void* const* d_in, const int* in_sizes, int n_in,
                              void* d_out, int out_size)
{
    (void)in_sizes; (void)n_in; (void)out_size;
    const float* x      = (const float*)d_in[0];
    const float* W_attn = (const float*)d_in[1];
    const float* b_attn = (const float*)d_in[2];
    const float* W_proj = (const float*)d_in[3];
    const float* b_proj = (const float*)d_in[4];
    float* out = (float*)d_out;

    void *qh = 0, *ql = 0, *ahp = 0, *alp = 0, *bhp = 0, *blp = 0;
    cudaGetSymbolAddress(&qh, g_qkvh);
    cudaGetSymbolAddress(&ql, g_qkvl);
    cudaGetSymbolAddress(&ahp, g_ah);
    cudaGetSymbolAddress(&alp, g_al);
    cudaGetSymbolAddress(&bhp, g_bh);
    cudaGetSymbolAddress(&blp, g_bl);

    cudaFuncSetAttribute(attn3_kernel,
                         cudaFuncAttributeMaxDynamicSharedMemorySize,
                         AT3_SMEM_BYTES);

    dim3 blk(256);

    // split x and W_attn into bf16 hi/lo planes
    split_kernel<<<(ROWS_ * M_) / 1024, blk>>>(
        x, (__nv_bfloat16*)ahp, (__nv_bfloat16*)alp);
    split_kernel<<<(M_ * N3M_) / 1024, blk>>>(
        W_attn, (__nv_bfloat16*)bhp, (__nv_bfloat16*)blp);

    // QKV projection -> bf16 hi/lo planes (Q pre-scaled by 0.125)
    gemm_bf16x3_t<1><<<dim3(N3M_ / 128, ROWS_ / 128), blk>>>(
        (const __nv_bfloat16*)ahp, (const __nv_bfloat16*)alp,
        (const __nv_bfloat16*)bhp, (const __nv_bfloat16*)blp,
        b_attn, nullptr,
        (__nv_bfloat16*)qh, (__nv_bfloat16*)ql, N3M_, M_);

    // tensor-core causal attention -> z hi/lo planes
    attn3_kernel<<<dim3(P_ / 128, B_ * H_), blk, AT3_SMEM_BYTES>>>(
        (const __nv_bfloat16*)qh, (const __nv_bfloat16*)ql,
        (__nv_bfloat16*)ahp, (__nv_bfloat16*)alp);

    // split W_proj
    split_kernel<<<(M_ * M_) / 1024, blk>>>(
        W_proj, (__nv_bfloat16*)bhp, (__nv_bfloat16*)blp);

    // output projection -> fp32 out
    gemm_bf16x3_t<0><<<dim3(M_ / 128, ROWS_ / 128), blk>>>(
        (const __nv_bfloat16*)ahp, (const __nv_bfloat16*)alp,
        (const __nv_bfloat16*)bhp, (const __nv_bfloat16*)blp,
        b_proj, out, nullptr, nullptr, M_, M_);
}